// round 7
// baseline (speedup 1.0000x reference)
#include <cuda_runtime.h>
#include <cstdint>

// Problem constants
#define BATCH    8
#define N_NODES  8192
#define CH       128
#define NEXP     64
#define NODES_PER_CHUNK 16
#define MAX_PAD  9216
#define MAX_CHK  576

#define KT        32
#define ROW_BYTES 144                      // 32 tf32 + 16B pad -> conflict-free ldmatrix
#define STAGE     (2 * 128 * ROW_BYTES)    // 36864: A tile + B tile
#define NSTAGES   3
#define SMEM_NODE (NSTAGES * STAGE)        // 110592
#define SMEM_TOTAL (SMEM_NODE + 64)

#define PREP_CTAS 128
#define NODES_PER_PREP (N_NODES / PREP_CTAS)   // 64

// Scratch
__device__ int   g_sorted[MAX_PAD];
__device__ int   g_chunk_expert[MAX_CHK];
__device__ int   g_hist_part[PREP_CTAS * NEXP];
__device__ int   g_cnt[NEXP];
__device__ int   g_arrive;                 // monotonic ticket (replay-safe)
__device__ float g_Wr[NEXP * CH * CH];     // tf32-rounded W

// ---------------------------------------------------------------------------
// helpers
// ---------------------------------------------------------------------------
__device__ __forceinline__ uint32_t smem_u32(const void* p) {
    uint32_t a;
    asm("{ .reg .u64 t; cvta.to.shared.u64 t, %1; cvt.u32.u64 %0, t; }"
        : "=r"(a) : "l"(p));
    return a;
}

__device__ __forceinline__ unsigned f2tf32(float f) {
    unsigned u;
    asm("cvt.rna.tf32.f32 %0, %1;" : "=r"(u) : "f"(f));
    return u;
}

__device__ __forceinline__ void cp16(uint32_t dst, const void* src, int sz) {
    asm volatile("cp.async.cg.shared.global [%0], [%1], 16, %2;"
                 :: "r"(dst), "l"(src), "r"(sz) : "memory");
}
__device__ __forceinline__ void cp_commit() {
    asm volatile("cp.async.commit_group;" ::: "memory");
}
template <int N>
__device__ __forceinline__ void cp_wait() {
    asm volatile("cp.async.wait_group %0;" :: "n"(N) : "memory");
}

__device__ __forceinline__ void ldsm_x4(uint32_t* r, uint32_t addr) {
    asm volatile("ldmatrix.sync.aligned.m8n8.x4.shared.b16 {%0,%1,%2,%3}, [%4];"
                 : "=r"(r[0]), "=r"(r[1]), "=r"(r[2]), "=r"(r[3])
                 : "r"(addr));
}

__device__ __forceinline__ void mma_tf32(float* d, const uint32_t* a, const uint32_t* b) {
    asm volatile(
        "mma.sync.aligned.m16n8k8.row.col.f32.tf32.tf32.f32 "
        "{%0,%1,%2,%3}, {%4,%5,%6,%7}, {%8,%9}, {%0,%1,%2,%3};\n"
        : "+f"(d[0]), "+f"(d[1]), "+f"(d[2]), "+f"(d[3])
        : "r"(a[0]), "r"(a[1]), "r"(a[2]), "r"(a[3]),
          "r"(b[0]), "r"(b[1]));
}

// ---------------------------------------------------------------------------
// K_prep (128 CTAs x 256, all co-resident): W rounding + dtype detect +
// histogram + grid barrier + scan + scatter + pads + chunk map. One launch.
// ---------------------------------------------------------------------------
__global__ __launch_bounds__(256, 1)
void prep_kernel(const float* __restrict__ W,
                 const long long* __restrict__ sel64) {
    const int tid = threadIdx.x;
    const int bid = blockIdx.x;

    __shared__ int lhist[NEXP];
    __shared__ int se[NODES_PER_PREP];
    __shared__ int hist[NEXP];
    __shared__ int sc[NEXP];
    __shared__ int pads[NEXP];
    __shared__ int rbase[NEXP];
    __shared__ int bad;
    __shared__ int ticket;

    // ---- Phase A: W rounding (2048 float4 per CTA) ----
#pragma unroll
    for (int j = 0; j < 8; j++) {
        int i = bid * 2048 + j * 256 + tid;
        float4 v = ((const float4*)W)[i];
        uint4 t;
        t.x = f2tf32(v.x); t.y = f2tf32(v.y);
        t.z = f2tf32(v.z); t.w = f2tf32(v.w);
        ((uint4*)g_Wr)[i] = t;
    }

    if (bid == 0 && tid < NEXP) g_cnt[tid] = 0;

    // ---- dtype detect over first 4096 int64 words (32KB: safe either way) ----
    if (tid == 0) bad = 0;
    if (tid < NEXP) lhist[tid] = 0;
    __syncthreads();
    int lbad = 0;
    for (int i = tid; i < 4096; i += 256) {
        long long v = sel64[i];
        if (v < 0 || v >= NEXP) lbad = 1;
    }
    if (lbad) atomicOr(&bad, 1);
    __syncthreads();
    const int is64 = bad ? 0 : 1;
    const int* sel32 = (const int*)sel64;

    // ---- local histogram of my 64 nodes ----
    if (tid < NODES_PER_PREP) {
        int n = bid * NODES_PER_PREP + tid;
        int e = is64 ? (int)sel64[n] : sel32[n];
        se[tid] = e;
        atomicAdd(&lhist[e], 1);
    }
    __syncthreads();
    if (tid < NEXP) g_hist_part[bid * NEXP + tid] = lhist[tid];
    __threadfence();

    // ---- grid barrier (monotonic ticket; 128 CTAs co-resident) ----
    __syncthreads();
    if (tid == 0) ticket = atomicAdd(&g_arrive, 1);
    __syncthreads();
    const int target = (ticket / PREP_CTAS + 1) * PREP_CTAS;
    if (tid == 0) {
        while (*((volatile int*)&g_arrive) < target) { }
    }
    __syncthreads();
    __threadfence();

    // ---- Phase B: reduce partials, scan (all CTAs compute identically) ----
    if (tid < NEXP) {
        int s = 0;
#pragma unroll 8
        for (int p = 0; p < PREP_CTAS; p++) s += g_hist_part[p * NEXP + tid];
        hist[tid] = s;
        int pd = (s + NODES_PER_CHUNK - 1) & ~(NODES_PER_CHUNK - 1);
        pads[tid] = pd;
        sc[tid] = pd;
    }
    __syncthreads();
#pragma unroll
    for (int d = 1; d < NEXP; d <<= 1) {
        int t = 0;
        if (tid < NEXP && tid >= d) t = sc[tid - d];
        __syncthreads();
        if (tid < NEXP) sc[tid] += t;
        __syncthreads();
    }
    // offs[e] = sc[e] - pads[e]

    // ---- CTA-specific outputs ----
    if (bid == 0) {
        // chunk map: expert tid writes its chunk range; others -1
        if (tid < NEXP) {
            int c0 = (sc[tid] - pads[tid]) / NODES_PER_CHUNK;
            int c1 = sc[tid] / NODES_PER_CHUNK;
            for (int c = c0; c < c1; c++) g_chunk_expert[c] = tid;
        }
        __syncthreads();
        int total_chunks = sc[NEXP - 1] / NODES_PER_CHUNK;
        for (int c = total_chunks + tid; c < MAX_CHK; c += 256)
            g_chunk_expert[c] = -1;
    }
    if (bid == 1 && tid < NEXP) {
        // pad slots -> -1 (disjoint from scatter targets)
        int lo = sc[tid] - pads[tid] + hist[tid];
        int hi = sc[tid];
        for (int i = lo; i < hi; i++) g_sorted[i] = -1;
    }

    // ---- reserve per-expert blocks, scatter my nodes by local rank ----
    if (tid < NEXP && lhist[tid] > 0)
        rbase[tid] = (sc[tid] - pads[tid]) + atomicAdd(&g_cnt[tid], lhist[tid]);
    __syncthreads();
    if (tid < NODES_PER_PREP) {
        int e = se[tid];
        int rank = 0;
        for (int j = 0; j < tid; j++) rank += (se[j] == e);
        g_sorted[rbase[e] + rank] = bid * NODES_PER_PREP + tid;
    }
}

// ---------------------------------------------------------------------------
// K_gemm: grouped GEMM, tf32 mma.sync + ldmatrix + 3-stage cp.async pipe.
// CTA 128(M) x 128(N) x 128(K in 4 tiles of 32). 8 warps, warp tile 32x64.
// (unchanged from R6 — control for this round)
// ---------------------------------------------------------------------------
extern __shared__ char smem[];

__global__ __launch_bounds__(256, 2)
void grouped_gemm_kernel(const float* __restrict__ x,
                         float* __restrict__ out) {
    const int e = g_chunk_expert[blockIdx.x];
    if (e < 0) return;

    int* snode = (int*)(smem + SMEM_NODE);
    const int tid  = threadIdx.x;
    const int lane = tid & 31;
    const int warp = tid >> 5;
    const int warp_m = (warp & 3) * 32;
    const int warp_n = (warp >> 2) * 64;

    if (tid < NODES_PER_CHUNK)
        snode[tid] = g_sorted[blockIdx.x * NODES_PER_CHUNK + tid];
    __syncthreads();

    const uint32_t sbase = smem_u32(smem);

    const float* xa[4];
    const float* wa[4];
    uint32_t da[4], db[4];
    int      asz[4];
    const float* Wre = g_Wr + (size_t)e * CH * CH;
#pragma unroll
    for (int i = 0; i < 4; i++) {
        int id  = tid + i * 256;
        int row = id >> 3;
        int cq  = id & 7;
        int node = snode[row >> 3];
        asz[i] = (node >= 0) ? 16 : 0;
        if (node < 0) node = 0;
        xa[i] = x + ((size_t)(row & 7) * N_NODES + node) * CH + cq * 4;
        wa[i] = Wre + (size_t)row * CH + cq * 4;
        da[i] = sbase + (uint32_t)row * ROW_BYTES + cq * 16;
        db[i] = sbase + (uint32_t)(128 * ROW_BYTES) + (uint32_t)row * ROW_BYTES + cq * 16;
    }

    uint32_t a_addr[2], b_addr[4];
    {
        int arow  = warp_m + (lane & 15);
        int abyte = (lane >> 4) * 16;
#pragma unroll
        for (int mt = 0; mt < 2; mt++)
            a_addr[mt] = sbase + (uint32_t)(arow + mt * 16) * ROW_BYTES + abyte;

        int brow  = warp_n + ((lane >> 4) << 3) + (lane & 7);
        int bbyte = ((lane >> 3) & 1) * 16;
#pragma unroll
        for (int p = 0; p < 4; p++)
            b_addr[p] = sbase + (uint32_t)(128 * ROW_BYTES)
                      + (uint32_t)(brow + p * 16) * ROW_BYTES + bbyte;
    }

    float acc[2][8][4];
#pragma unroll
    for (int mt = 0; mt < 2; mt++)
#pragma unroll
        for (int nt = 0; nt < 8; nt++)
#pragma unroll
            for (int i = 0; i < 4; i++) acc[mt][nt][i] = 0.0f;

#pragma unroll
    for (int t = 0; t < 2; t++) {
        uint32_t so = t * STAGE;
        int go = t * KT;
#pragma unroll
        for (int i = 0; i < 4; i++) {
            cp16(da[i] + so, xa[i] + go, asz[i]);
            cp16(db[i] + so, wa[i] + go, 16);
        }
        cp_commit();
    }

#pragma unroll
    for (int k = 0; k < 4; k++) {
        if (k + 2 < 4) {
            uint32_t so = ((k + 2) % NSTAGES) * STAGE;
            int go = (k + 2) * KT;
#pragma unroll
            for (int i = 0; i < 4; i++) {
                cp16(da[i] + so, xa[i] + go, asz[i]);
                cp16(db[i] + so, wa[i] + go, 16);
            }
            cp_commit();
        }
        if (k <= 1)      cp_wait<2>();
        else if (k == 2) cp_wait<1>();
        else             cp_wait<0>();
        __syncthreads();

        const uint32_t so = (k % NSTAGES) * STAGE;
#pragma unroll
        for (int ks = 0; ks < 4; ks++) {
            uint32_t a[2][4], b[4][4];
#pragma unroll
            for (int mt = 0; mt < 2; mt++)
                ldsm_x4(a[mt], a_addr[mt] + so + ks * 32);
#pragma unroll
            for (int p = 0; p < 4; p++)
                ldsm_x4(b[p], b_addr[p] + so + ks * 32);
#pragma unroll
            for (int mt = 0; mt < 2; mt++)
#pragma unroll
                for (int nt = 0; nt < 8; nt++)
                    mma_tf32(acc[mt][nt], a[mt], &b[nt >> 1][(nt & 1) * 2]);
        }
        __syncthreads();
    }

    const int g = lane >> 2;
    const int c = lane & 3;
#pragma unroll
    for (int mt = 0; mt < 2; mt++) {
#pragma unroll
        for (int half = 0; half < 2; half++) {
            int r = warp_m + mt * 16 + g + half * 8;
            int node = snode[r >> 3];
            if (node < 0) continue;
            float* o = out + ((size_t)(r & 7) * N_NODES + node) * CH + warp_n;
#pragma unroll
            for (int nt = 0; nt < 8; nt++) {
                float2 v2 = make_float2(acc[mt][nt][half * 2],
                                        acc[mt][nt][half * 2 + 1]);
                *(float2*)(o + nt * 8 + c * 2) = v2;
            }
        }
    }
}

// ---------------------------------------------------------------------------
extern "C" void kernel_launch(void* const* d_in, const int* in_sizes, int n_in,
                              void* d_out, int out_size) {
    const float*     x   = (const float*)d_in[0];
    const long long* sel = (const long long*)d_in[1];
    const float*     W   = (const float*)d_in[2];
    float*           out = (float*)d_out;

    static bool attr_set = false;
    if (!attr_set) {
        cudaFuncSetAttribute(grouped_gemm_kernel,
                             cudaFuncAttributeMaxDynamicSharedMemorySize,
                             SMEM_TOTAL);
        attr_set = true;
    }

    prep_kernel<<<PREP_CTAS, 256>>>(W, sel);
    grouped_gemm_kernel<<<MAX_CHK, 256, SMEM_TOTAL>>>(x, out);
}

// round 8
// speedup vs baseline: 1.0073x; 1.0073x over previous
#include <cuda_runtime.h>
#include <cstdint>

// Problem constants
#define N_NODES  8192
#define CH       128
#define NEXP     64
#define NODES_PER_CHUNK 16
#define MAX_PAD  9216
#define MAX_CHK  576

#define KT        32
#define ROW_BYTES 144                      // 32 words + 16B pad -> conflict-free ldmatrix
#define STAGE     (2 * 128 * ROW_BYTES)    // 36864: A tile + B tile
#define NSTAGES   3
#define SMEM_NODE (NSTAGES * STAGE)        // 110592
#define SMEM_TOTAL (SMEM_NODE + 64)

#define HIST_CTAS 32
#define NODES_PER_HIST (N_NODES / HIST_CTAS)   // 256

// Scratch (no init required: hist partials are plain-stored every run;
// g_sorted/-chunk map fully rewritten by scatter_kernel every run)
__device__ int g_sorted[MAX_PAD];
__device__ int g_chunk_expert[MAX_CHK];
__device__ int g_hist_part[HIST_CTAS * NEXP];

// ---------------------------------------------------------------------------
// helpers
// ---------------------------------------------------------------------------
__device__ __forceinline__ uint32_t smem_u32(const void* p) {
    uint32_t a;
    asm("{ .reg .u64 t; cvta.to.shared.u64 t, %1; cvt.u32.u64 %0, t; }"
        : "=r"(a) : "l"(p));
    return a;
}

__device__ __forceinline__ uint32_t f2tf32(float f) {
    uint32_t u;
    asm("cvt.rna.tf32.f32 %0, %1;" : "=r"(u) : "f"(f));
    return u;
}

__device__ __forceinline__ void cp16(uint32_t dst, const void* src, int sz) {
    asm volatile("cp.async.cg.shared.global [%0], [%1], 16, %2;"
                 :: "r"(dst), "l"(src), "r"(sz) : "memory");
}
__device__ __forceinline__ void cp_commit() {
    asm volatile("cp.async.commit_group;" ::: "memory");
}
template <int N>
__device__ __forceinline__ void cp_wait() {
    asm volatile("cp.async.wait_group %0;" :: "n"(N) : "memory");
}

__device__ __forceinline__ void ldsm_x4(uint32_t* r, uint32_t addr) {
    asm volatile("ldmatrix.sync.aligned.m8n8.x4.shared.b16 {%0,%1,%2,%3}, [%4];"
                 : "=r"(r[0]), "=r"(r[1]), "=r"(r[2]), "=r"(r[3])
                 : "r"(addr));
}

__device__ __forceinline__ void mma_tf32(float* d, const uint32_t* a, const uint32_t* b) {
    asm volatile(
        "mma.sync.aligned.m16n8k8.row.col.f32.tf32.tf32.f32 "
        "{%0,%1,%2,%3}, {%4,%5,%6,%7}, {%8,%9}, {%0,%1,%2,%3};\n"
        : "+f"(d[0]), "+f"(d[1]), "+f"(d[2]), "+f"(d[3])
        : "r"(a[0]), "r"(a[1]), "r"(a[2]), "r"(a[3]),
          "r"(b[0]), "r"(b[1]));
}

// dtype detect: scan first 2048 int64 words (16KB, safe for either dtype).
// Genuine int64 sel has all words in [0,64); int32 data aliased lands >=2^32
// unless its high half (a sel value) is 0 for ALL 2048 words: P=(1/64)^2048.
__device__ __forceinline__ int detect_is64(const long long* __restrict__ sel64,
                                           int tid, int* sh_bad) {
    if (tid == 0) *sh_bad = 0;
    __syncthreads();
    int lbad = 0;
    for (int i = tid; i < 2048; i += 256) {
        long long v = sel64[i];
        if (v < 0 || v >= NEXP) lbad = 1;
    }
    if (lbad) atomicOr(sh_bad, 1);
    __syncthreads();
    return *sh_bad ? 0 : 1;
}

// ---------------------------------------------------------------------------
// K_hist (32 CTAs x 256): per-CTA partial histogram, plain stores (no init).
// ---------------------------------------------------------------------------
__global__ void hist_kernel(const long long* __restrict__ sel64) {
    __shared__ int lh[NEXP];
    __shared__ int bad;
    const int tid = threadIdx.x;
    const int bid = blockIdx.x;
    if (tid < NEXP) lh[tid] = 0;
    const int is64 = detect_is64(sel64, tid, &bad);
    const int* sel32 = (const int*)sel64;

    int n = bid * NODES_PER_HIST + tid;
    int e = is64 ? (int)sel64[n] : sel32[n];
    atomicAdd(&lh[e], 1);
    __syncthreads();
    if (tid < NEXP) g_hist_part[bid * NEXP + tid] = lh[tid];
}

// ---------------------------------------------------------------------------
// K_scatter (32 CTAs x 256): each CTA redundantly reduces partials + scans;
// per-CTA slot ranges derived from partials of CTAs < bid (no global atomics).
// CTA0 writes chunk map; CTA1 writes -1 pads.
// ---------------------------------------------------------------------------
__global__ void scatter_kernel(const long long* __restrict__ sel64) {
    __shared__ int bad;
    __shared__ int hist[NEXP];
    __shared__ int pads[NEXP];
    __shared__ int sc[NEXP];      // inclusive scan of padded counts
    __shared__ int cursor[NEXP];  // this CTA's write cursor per expert
    const int tid = threadIdx.x;
    const int bid = blockIdx.x;

    const int is64 = detect_is64(sel64, tid, &bad);
    const int* sel32 = (const int*)sel64;

    int pre = 0;
    if (tid < NEXP) {
        int tot = 0;
#pragma unroll 8
        for (int p = 0; p < HIST_CTAS; p++) {
            int v = g_hist_part[p * NEXP + tid];
            tot += v;
            if (p < bid) pre += v;
        }
        hist[tid] = tot;
        int pd = (tot + NODES_PER_CHUNK - 1) & ~(NODES_PER_CHUNK - 1);
        pads[tid] = pd;
        sc[tid] = pd;
    }
    __syncthreads();
#pragma unroll
    for (int d = 1; d < NEXP; d <<= 1) {
        int t = 0;
        if (tid < NEXP && tid >= d) t = sc[tid - d];
        __syncthreads();
        if (tid < NEXP) sc[tid] += t;
        __syncthreads();
    }
    if (tid < NEXP) cursor[tid] = (sc[tid] - pads[tid]) + pre;   // offs[e] + pre
    __syncthreads();

    if (bid == 0) {
        if (tid < NEXP) {
            int c0 = (sc[tid] - pads[tid]) / NODES_PER_CHUNK;
            int c1 = sc[tid] / NODES_PER_CHUNK;
            for (int c = c0; c < c1; c++) g_chunk_expert[c] = tid;
        }
        __syncthreads();
        int total_chunks = sc[NEXP - 1] / NODES_PER_CHUNK;
        for (int c = total_chunks + tid; c < MAX_CHK; c += 256)
            g_chunk_expert[c] = -1;
    }
    if (bid == 1 && tid < NEXP) {
        int lo = sc[tid] - pads[tid] + hist[tid];
        int hi = sc[tid];
        for (int i = lo; i < hi; i++) g_sorted[i] = -1;
    }

    int n = bid * NODES_PER_HIST + tid;
    int e = is64 ? (int)sel64[n] : sel32[n];
    int pos = atomicAdd(&cursor[e], 1);     // smem atomic; disjoint ranges per CTA
    g_sorted[pos] = n;
}

// ---------------------------------------------------------------------------
// K_gemm: grouped GEMM, tf32 mma.sync + ldmatrix + 3-stage cp.async pipe.
// Raw fp32 A and B loaded; fragments cvt.rna.tf32 in-register (unbiased).
// CTA 128(M) x 128(N) x 128(K in 4 tiles of 32). 8 warps, warp tile 32x64.
// ---------------------------------------------------------------------------
extern __shared__ char smem[];

__global__ __launch_bounds__(256, 2)
void grouped_gemm_kernel(const float* __restrict__ x,
                         const float* __restrict__ W,
                         float* __restrict__ out) {
    const int e = g_chunk_expert[blockIdx.x];
    if (e < 0) return;

    int* snode = (int*)(smem + SMEM_NODE);
    const int tid  = threadIdx.x;
    const int lane = tid & 31;
    const int warp = tid >> 5;
    const int warp_m = (warp & 3) * 32;
    const int warp_n = (warp >> 2) * 64;

    if (tid < NODES_PER_CHUNK)
        snode[tid] = g_sorted[blockIdx.x * NODES_PER_CHUNK + tid];
    __syncthreads();

    const uint32_t sbase = smem_u32(smem);

    const float* xa[4];
    const float* wa[4];
    uint32_t da[4], db[4];
    int      asz[4];
    const float* We = W + (size_t)e * CH * CH;
#pragma unroll
    for (int i = 0; i < 4; i++) {
        int id  = tid + i * 256;
        int row = id >> 3;
        int cq  = id & 7;
        int node = snode[row >> 3];
        asz[i] = (node >= 0) ? 16 : 0;
        if (node < 0) node = 0;
        xa[i] = x + ((size_t)(row & 7) * N_NODES + node) * CH + cq * 4;
        wa[i] = We + (size_t)row * CH + cq * 4;
        da[i] = sbase + (uint32_t)row * ROW_BYTES + cq * 16;
        db[i] = sbase + (uint32_t)(128 * ROW_BYTES) + (uint32_t)row * ROW_BYTES + cq * 16;
    }

    uint32_t a_addr[2], b_addr[4];
    {
        int arow  = warp_m + (lane & 15);
        int abyte = (lane >> 4) * 16;
#pragma unroll
        for (int mt = 0; mt < 2; mt++)
            a_addr[mt] = sbase + (uint32_t)(arow + mt * 16) * ROW_BYTES + abyte;

        int brow  = warp_n + ((lane >> 4) << 3) + (lane & 7);
        int bbyte = ((lane >> 3) & 1) * 16;
#pragma unroll
        for (int p = 0; p < 4; p++)
            b_addr[p] = sbase + (uint32_t)(128 * ROW_BYTES)
                      + (uint32_t)(brow + p * 16) * ROW_BYTES + bbyte;
    }

    float acc[2][8][4];
#pragma unroll
    for (int mt = 0; mt < 2; mt++)
#pragma unroll
        for (int nt = 0; nt < 8; nt++)
#pragma unroll
            for (int i = 0; i < 4; i++) acc[mt][nt][i] = 0.0f;

#pragma unroll
    for (int t = 0; t < 2; t++) {
        uint32_t so = t * STAGE;
        int go = t * KT;
#pragma unroll
        for (int i = 0; i < 4; i++) {
            cp16(da[i] + so, xa[i] + go, asz[i]);
            cp16(db[i] + so, wa[i] + go, 16);
        }
        cp_commit();
    }

#pragma unroll
    for (int k = 0; k < 4; k++) {
        if (k + 2 < 4) {
            uint32_t so = ((k + 2) % NSTAGES) * STAGE;
            int go = (k + 2) * KT;
#pragma unroll
            for (int i = 0; i < 4; i++) {
                cp16(da[i] + so, xa[i] + go, asz[i]);
                cp16(db[i] + so, wa[i] + go, 16);
            }
            cp_commit();
        }
        if (k <= 1)      cp_wait<2>();
        else if (k == 2) cp_wait<1>();
        else             cp_wait<0>();
        __syncthreads();

        const uint32_t so = (k % NSTAGES) * STAGE;
#pragma unroll
        for (int ks = 0; ks < 4; ks++) {
            uint32_t a[2][4], b[4][4];
#pragma unroll
            for (int mt = 0; mt < 2; mt++)
                ldsm_x4(a[mt], a_addr[mt] + so + ks * 32);
#pragma unroll
            for (int p = 0; p < 4; p++)
                ldsm_x4(b[p], b_addr[p] + so + ks * 32);

            // unbiased tf32 rounding of raw fp32 fragments (replaces the
            // W pre-round pass AND removes x truncation bias)
#pragma unroll
            for (int mt = 0; mt < 2; mt++)
#pragma unroll
                for (int i = 0; i < 4; i++)
                    a[mt][i] = f2tf32(__uint_as_float(a[mt][i]));
#pragma unroll
            for (int p = 0; p < 4; p++)
#pragma unroll
                for (int i = 0; i < 4; i++)
                    b[p][i] = f2tf32(__uint_as_float(b[p][i]));

#pragma unroll
            for (int mt = 0; mt < 2; mt++)
#pragma unroll
                for (int nt = 0; nt < 8; nt++)
                    mma_tf32(acc[mt][nt], a[mt], &b[nt >> 1][(nt & 1) * 2]);
        }
        __syncthreads();
    }

    const int g = lane >> 2;
    const int c = lane & 3;
#pragma unroll
    for (int mt = 0; mt < 2; mt++) {
#pragma unroll
        for (int half = 0; half < 2; half++) {
            int r = warp_m + mt * 16 + g + half * 8;
            int node = snode[r >> 3];
            if (node < 0) continue;
            float* o = out + ((size_t)(r & 7) * N_NODES + node) * CH + warp_n;
#pragma unroll
            for (int nt = 0; nt < 8; nt++) {
                float2 v2 = make_float2(acc[mt][nt][half * 2],
                                        acc[mt][nt][half * 2 + 1]);
                *(float2*)(o + nt * 8 + c * 2) = v2;
            }
        }
    }
}

// ---------------------------------------------------------------------------
extern "C" void kernel_launch(void* const* d_in, const int* in_sizes, int n_in,
                              void* d_out, int out_size) {
    const float*     x   = (const float*)d_in[0];
    const long long* sel = (const long long*)d_in[1];
    const float*     W   = (const float*)d_in[2];
    float*           out = (float*)d_out;

    static bool attr_set = false;
    if (!attr_set) {
        cudaFuncSetAttribute(grouped_gemm_kernel,
                             cudaFuncAttributeMaxDynamicSharedMemorySize,
                             SMEM_TOTAL);
        attr_set = true;
    }

    hist_kernel<<<HIST_CTAS, 256>>>(sel);
    scatter_kernel<<<HIST_CTAS, 256>>>(sel);
    grouped_gemm_kernel<<<MAX_CHK, 256, SMEM_TOTAL>>>(x, W, out);
}

// round 9
// speedup vs baseline: 1.0193x; 1.0119x over previous
#include <cuda_runtime.h>
#include <cstdint>

// Problem constants
#define N_NODES  8192
#define CH       128
#define NEXP     64
#define NODES_PER_CHUNK 16
#define MAX_PAD  9216
#define MAX_CHK  576

#define KT        32
#define ROW_BYTES 144                      // 32 words + 16B pad -> conflict-free ldmatrix
#define STAGE     (2 * 128 * ROW_BYTES)    // 36864: A tile + B tile
#define NSTAGES   3
#define SMEM_NODE (NSTAGES * STAGE)        // 110592
#define SMEM_TOTAL (SMEM_NODE + 64)

#define HIST_CTAS 32
#define NODES_PER_HIST (N_NODES / HIST_CTAS)   // 256

// Scratch
__device__ int   g_sorted[MAX_PAD];
__device__ int   g_chunk_expert[MAX_CHK];
__device__ int   g_hist_part[HIST_CTAS * NEXP];
__device__ float g_Wr[NEXP * CH * CH];     // tf32-rounded W

// ---------------------------------------------------------------------------
// helpers
// ---------------------------------------------------------------------------
__device__ __forceinline__ uint32_t smem_u32(const void* p) {
    uint32_t a;
    asm("{ .reg .u64 t; cvta.to.shared.u64 t, %1; cvt.u32.u64 %0, t; }"
        : "=r"(a) : "l"(p));
    return a;
}

__device__ __forceinline__ uint32_t f2tf32(float f) {
    uint32_t u;
    asm("cvt.rna.tf32.f32 %0, %1;" : "=r"(u) : "f"(f));
    return u;
}

__device__ __forceinline__ void cp16(uint32_t dst, const void* src, int sz) {
    asm volatile("cp.async.cg.shared.global [%0], [%1], 16, %2;"
                 :: "r"(dst), "l"(src), "r"(sz) : "memory");
}
__device__ __forceinline__ void cp_commit() {
    asm volatile("cp.async.commit_group;" ::: "memory");
}
template <int N>
__device__ __forceinline__ void cp_wait() {
    asm volatile("cp.async.wait_group %0;" :: "n"(N) : "memory");
}

__device__ __forceinline__ void ldsm_x4(uint32_t* r, uint32_t addr) {
    asm volatile("ldmatrix.sync.aligned.m8n8.x4.shared.b16 {%0,%1,%2,%3}, [%4];"
                 : "=r"(r[0]), "=r"(r[1]), "=r"(r[2]), "=r"(r[3])
                 : "r"(addr));
}

__device__ __forceinline__ void mma_tf32(float* d, const uint32_t* a, const uint32_t* b) {
    asm volatile(
        "mma.sync.aligned.m16n8k8.row.col.f32.tf32.tf32.f32 "
        "{%0,%1,%2,%3}, {%4,%5,%6,%7}, {%8,%9}, {%0,%1,%2,%3};\n"
        : "+f"(d[0]), "+f"(d[1]), "+f"(d[2]), "+f"(d[3])
        : "r"(a[0]), "r"(a[1]), "r"(a[2]), "r"(a[3]),
          "r"(b[0]), "r"(b[1]));
}

// dtype detect: scan first 2048 int64 words (16KB, safe for either dtype).
__device__ __forceinline__ int detect_is64(const long long* __restrict__ sel64,
                                           int tid, int* sh_bad) {
    if (tid == 0) *sh_bad = 0;
    __syncthreads();
    int lbad = 0;
    for (int i = tid; i < 2048; i += 256) {
        long long v = sel64[i];
        if (v < 0 || v >= NEXP) lbad = 1;
    }
    if (lbad) atomicOr(sh_bad, 1);
    __syncthreads();
    return *sh_bad ? 0 : 1;
}

// ---------------------------------------------------------------------------
// K_wround (128 CTAs x 256, parallel stream): W -> tf32-rounded g_Wr.
// ---------------------------------------------------------------------------
__global__ void wround_kernel(const float* __restrict__ W) {
    const int base = blockIdx.x * 2048 + threadIdx.x;
#pragma unroll
    for (int j = 0; j < 8; j++) {
        int i = base + j * 256;
        float4 v = ((const float4*)W)[i];
        uint4 t;
        t.x = f2tf32(v.x); t.y = f2tf32(v.y);
        t.z = f2tf32(v.z); t.w = f2tf32(v.w);
        ((uint4*)g_Wr)[i] = t;
    }
}

// ---------------------------------------------------------------------------
// K_hist (32 CTAs x 256): per-CTA partial histogram, plain stores (no init).
// ---------------------------------------------------------------------------
__global__ void hist_kernel(const long long* __restrict__ sel64) {
    __shared__ int lh[NEXP];
    __shared__ int bad;
    const int tid = threadIdx.x;
    const int bid = blockIdx.x;
    if (tid < NEXP) lh[tid] = 0;
    const int is64 = detect_is64(sel64, tid, &bad);
    const int* sel32 = (const int*)sel64;

    int n = bid * NODES_PER_HIST + tid;
    int e = is64 ? (int)sel64[n] : sel32[n];
    atomicAdd(&lh[e], 1);
    __syncthreads();
    if (tid < NEXP) g_hist_part[bid * NEXP + tid] = lh[tid];
}

// ---------------------------------------------------------------------------
// K_scatter (32 CTAs x 256): redundant reduce+scan; per-CTA slot ranges from
// partials of CTAs < bid (no global atomics). CTA0: chunk map; CTA1: -1 pads.
// ---------------------------------------------------------------------------
__global__ void scatter_kernel(const long long* __restrict__ sel64) {
    __shared__ int bad;
    __shared__ int hist[NEXP];
    __shared__ int pads[NEXP];
    __shared__ int sc[NEXP];
    __shared__ int cursor[NEXP];
    const int tid = threadIdx.x;
    const int bid = blockIdx.x;

    const int is64 = detect_is64(sel64, tid, &bad);
    const int* sel32 = (const int*)sel64;

    int pre = 0;
    if (tid < NEXP) {
        int tot = 0;
#pragma unroll 8
        for (int p = 0; p < HIST_CTAS; p++) {
            int v = g_hist_part[p * NEXP + tid];
            tot += v;
            if (p < bid) pre += v;
        }
        hist[tid] = tot;
        int pd = (tot + NODES_PER_CHUNK - 1) & ~(NODES_PER_CHUNK - 1);
        pads[tid] = pd;
        sc[tid] = pd;
    }
    __syncthreads();
#pragma unroll
    for (int d = 1; d < NEXP; d <<= 1) {
        int t = 0;
        if (tid < NEXP && tid >= d) t = sc[tid - d];
        __syncthreads();
        if (tid < NEXP) sc[tid] += t;
        __syncthreads();
    }
    if (tid < NEXP) cursor[tid] = (sc[tid] - pads[tid]) + pre;
    __syncthreads();

    if (bid == 0) {
        if (tid < NEXP) {
            int c0 = (sc[tid] - pads[tid]) / NODES_PER_CHUNK;
            int c1 = sc[tid] / NODES_PER_CHUNK;
            for (int c = c0; c < c1; c++) g_chunk_expert[c] = tid;
        }
        __syncthreads();
        int total_chunks = sc[NEXP - 1] / NODES_PER_CHUNK;
        for (int c = total_chunks + tid; c < MAX_CHK; c += 256)
            g_chunk_expert[c] = -1;
    }
    if (bid == 1 && tid < NEXP) {
        int lo = sc[tid] - pads[tid] + hist[tid];
        int hi = sc[tid];
        for (int i = lo; i < hi; i++) g_sorted[i] = -1;
    }

    int n = bid * NODES_PER_HIST + tid;
    int e = is64 ? (int)sel64[n] : sel32[n];
    int pos = atomicAdd(&cursor[e], 1);     // smem atomic; disjoint ranges per CTA
    g_sorted[pos] = n;
}

// ---------------------------------------------------------------------------
// K_gemm: grouped GEMM (R6-proven), tf32 mma.sync + ldmatrix + 3-stage
// cp.async, pre-rounded W. Single __syncthreads per k-tile:
//   wait -> sync -> issue(k+2) -> compute(k)
// Stage written at iter k is (k+2)%3 == (k-1)%3, whose readers all passed
// this iteration's barrier.
// ---------------------------------------------------------------------------
extern __shared__ char smem[];

__global__ __launch_bounds__(256, 2)
void grouped_gemm_kernel(const float* __restrict__ x,
                         float* __restrict__ out) {
    const int e = g_chunk_expert[blockIdx.x];
    if (e < 0) return;

    int* snode = (int*)(smem + SMEM_NODE);
    const int tid  = threadIdx.x;
    const int lane = tid & 31;
    const int warp = tid >> 5;
    const int warp_m = (warp & 3) * 32;
    const int warp_n = (warp >> 2) * 64;

    if (tid < NODES_PER_CHUNK)
        snode[tid] = g_sorted[blockIdx.x * NODES_PER_CHUNK + tid];
    __syncthreads();

    const uint32_t sbase = smem_u32(smem);

    const float* xa[4];
    const float* wa[4];
    uint32_t da[4], db[4];
    int      asz[4];
    const float* Wre = g_Wr + (size_t)e * CH * CH;
#pragma unroll
    for (int i = 0; i < 4; i++) {
        int id  = tid + i * 256;
        int row = id >> 3;
        int cq  = id & 7;
        int node = snode[row >> 3];
        asz[i] = (node >= 0) ? 16 : 0;
        if (node < 0) node = 0;
        xa[i] = x + ((size_t)(row & 7) * N_NODES + node) * CH + cq * 4;
        wa[i] = Wre + (size_t)row * CH + cq * 4;
        da[i] = sbase + (uint32_t)row * ROW_BYTES + cq * 16;
        db[i] = sbase + (uint32_t)(128 * ROW_BYTES) + (uint32_t)row * ROW_BYTES + cq * 16;
    }

    uint32_t a_addr[2], b_addr[4];
    {
        int arow  = warp_m + (lane & 15);
        int abyte = (lane >> 4) * 16;
#pragma unroll
        for (int mt = 0; mt < 2; mt++)
            a_addr[mt] = sbase + (uint32_t)(arow + mt * 16) * ROW_BYTES + abyte;

        int brow  = warp_n + ((lane >> 4) << 3) + (lane & 7);
        int bbyte = ((lane >> 3) & 1) * 16;
#pragma unroll
        for (int p = 0; p < 4; p++)
            b_addr[p] = sbase + (uint32_t)(128 * ROW_BYTES)
                      + (uint32_t)(brow + p * 16) * ROW_BYTES + bbyte;
    }

    float acc[2][8][4];
#pragma unroll
    for (int mt = 0; mt < 2; mt++)
#pragma unroll
        for (int nt = 0; nt < 8; nt++)
#pragma unroll
            for (int i = 0; i < 4; i++) acc[mt][nt][i] = 0.0f;

    // prologue: issue tiles 0 and 1
#pragma unroll
    for (int t = 0; t < 2; t++) {
        uint32_t so = t * STAGE;
        int go = t * KT;
#pragma unroll
        for (int i = 0; i < 4; i++) {
            cp16(da[i] + so, xa[i] + go, asz[i]);
            cp16(db[i] + so, wa[i] + go, 16);
        }
        cp_commit();
    }

#pragma unroll
    for (int k = 0; k < 4; k++) {
        if (k < 3) cp_wait<1>();
        else       cp_wait<0>();
        __syncthreads();

        if (k + 2 < 4) {
            uint32_t so = ((k + 2) % NSTAGES) * STAGE;
            int go = (k + 2) * KT;
#pragma unroll
            for (int i = 0; i < 4; i++) {
                cp16(da[i] + so, xa[i] + go, asz[i]);
                cp16(db[i] + so, wa[i] + go, 16);
            }
            cp_commit();
        }

        const uint32_t so = (k % NSTAGES) * STAGE;
#pragma unroll
        for (int ks = 0; ks < 4; ks++) {
            uint32_t a[2][4], b[4][4];
#pragma unroll
            for (int mt = 0; mt < 2; mt++)
                ldsm_x4(a[mt], a_addr[mt] + so + ks * 32);
#pragma unroll
            for (int p = 0; p < 4; p++)
                ldsm_x4(b[p], b_addr[p] + so + ks * 32);
#pragma unroll
            for (int mt = 0; mt < 2; mt++)
#pragma unroll
                for (int nt = 0; nt < 8; nt++)
                    mma_tf32(acc[mt][nt], a[mt], &b[nt >> 1][(nt & 1) * 2]);
        }
    }

    const int g = lane >> 2;
    const int c = lane & 3;
#pragma unroll
    for (int mt = 0; mt < 2; mt++) {
#pragma unroll
        for (int half = 0; half < 2; half++) {
            int r = warp_m + mt * 16 + g + half * 8;
            int node = snode[r >> 3];
            if (node < 0) continue;
            float* o = out + ((size_t)(r & 7) * N_NODES + node) * CH + warp_n;
#pragma unroll
            for (int nt = 0; nt < 8; nt++) {
                float2 v2 = make_float2(acc[mt][nt][half * 2],
                                        acc[mt][nt][half * 2 + 1]);
                *(float2*)(o + nt * 8 + c * 2) = v2;
            }
        }
    }
}

// ---------------------------------------------------------------------------
extern "C" void kernel_launch(void* const* d_in, const int* in_sizes, int n_in,
                              void* d_out, int out_size) {
    const float*     x   = (const float*)d_in[0];
    const long long* sel = (const long long*)d_in[1];
    const float*     W   = (const float*)d_in[2];
    float*           out = (float*)d_out;

    static cudaStream_t s2 = nullptr;
    static cudaEvent_t ev_fork = nullptr, ev_join = nullptr;
    if (s2 == nullptr) {   // first (uncaptured) correctness call
        cudaStreamCreateWithFlags(&s2, cudaStreamNonBlocking);
        cudaEventCreateWithFlags(&ev_fork, cudaEventDisableTiming);
        cudaEventCreateWithFlags(&ev_join, cudaEventDisableTiming);
        cudaFuncSetAttribute(grouped_gemm_kernel,
                             cudaFuncAttributeMaxDynamicSharedMemorySize,
                             SMEM_TOTAL);
    }

    // fork: W-rounding in parallel with hist -> scatter
    cudaEventRecord(ev_fork, 0);
    cudaStreamWaitEvent(s2, ev_fork, 0);
    wround_kernel<<<128, 256, 0, s2>>>(W);
    cudaEventRecord(ev_join, s2);

    hist_kernel<<<HIST_CTAS, 256>>>(sel);
    scatter_kernel<<<HIST_CTAS, 256>>>(sel);

    // join, then GEMM
    cudaStreamWaitEvent(0, ev_join, 0);
    grouped_gemm_kernel<<<MAX_CHK, 256, SMEM_TOTAL>>>(x, out);
}

// round 10
// speedup vs baseline: 1.2076x; 1.1848x over previous
#include <cuda_runtime.h>
#include <cstdint>

// Problem constants
#define N_NODES  8192
#define CH       128
#define NEXP     64
#define NODES_PER_CHUNK 16
#define MAX_PAD  9216
#define MAX_CHK  576

#define KT        32
#define ROW_BYTES 144                      // 32 words + 16B pad -> conflict-free ldmatrix
#define STAGE     (2 * 128 * ROW_BYTES)    // 36864: A tile + B tile
#define NSTAGES   3
#define SMEM_NODE (NSTAGES * STAGE)        // 110592
#define SMEM_TOTAL (SMEM_NODE + 64)

// Scratch
__device__ int   g_sorted[MAX_PAD];
__device__ int   g_chunk_expert[MAX_CHK];
__device__ float g_Wr[NEXP * CH * CH];     // tf32-rounded W

// ---------------------------------------------------------------------------
// helpers
// ---------------------------------------------------------------------------
__device__ __forceinline__ uint32_t smem_u32(const void* p) {
    uint32_t a;
    asm("{ .reg .u64 t; cvta.to.shared.u64 t, %1; cvt.u32.u64 %0, t; }"
        : "=r"(a) : "l"(p));
    return a;
}

__device__ __forceinline__ uint32_t f2tf32(float f) {
    uint32_t u;
    asm("cvt.rna.tf32.f32 %0, %1;" : "=r"(u) : "f"(f));
    return u;
}

__device__ __forceinline__ void cp16(uint32_t dst, const void* src, int sz) {
    asm volatile("cp.async.cg.shared.global [%0], [%1], 16, %2;"
                 :: "r"(dst), "l"(src), "r"(sz) : "memory");
}
__device__ __forceinline__ void cp_commit() {
    asm volatile("cp.async.commit_group;" ::: "memory");
}
template <int N>
__device__ __forceinline__ void cp_wait() {
    asm volatile("cp.async.wait_group %0;" :: "n"(N) : "memory");
}

__device__ __forceinline__ void ldsm_x4(uint32_t* r, uint32_t addr) {
    asm volatile("ldmatrix.sync.aligned.m8n8.x4.shared.b16 {%0,%1,%2,%3}, [%4];"
                 : "=r"(r[0]), "=r"(r[1]), "=r"(r[2]), "=r"(r[3])
                 : "r"(addr));
}

__device__ __forceinline__ void mma_tf32(float* d, const uint32_t* a, const uint32_t* b) {
    asm volatile(
        "mma.sync.aligned.m16n8k8.row.col.f32.tf32.tf32.f32 "
        "{%0,%1,%2,%3}, {%4,%5,%6,%7}, {%8,%9}, {%0,%1,%2,%3};\n"
        : "+f"(d[0]), "+f"(d[1]), "+f"(d[2]), "+f"(d[3])
        : "r"(a[0]), "r"(a[1]), "r"(a[2]), "r"(a[3]),
          "r"(b[0]), "r"(b[1]));
}

// ---------------------------------------------------------------------------
// K_prep (64 CTAs x 256): CTA e owns expert e. No cross-CTA dependencies.
//  - rounds its 1/64 slice of W to tf32
//  - detects sel dtype (64-word window = 512B; safe for min-size buffer)
//  - reads ALL of sel (L2-broadcast), full smem histogram, local scan
//  - compacts its own expert's nodes into g_sorted, writes pads + chunk map
// ---------------------------------------------------------------------------
__global__ __launch_bounds__(256, 2)
void prep_kernel(const float* __restrict__ W,
                 const long long* __restrict__ sel64) {
    const int tid = threadIdx.x;
    const int e   = blockIdx.x;

    __shared__ int bad;
    __shared__ int hist[NEXP];
    __shared__ int pads[NEXP];
    __shared__ int sc[NEXP];
    __shared__ int tc[256];

    // ---- W rounding slice: 4096 float4 per CTA, 16 per thread ----
#pragma unroll
    for (int j = 0; j < 16; j++) {
        int i = e * 4096 + j * 256 + tid;
        float4 v = ((const float4*)W)[j == 0 ? i : i];  // keep simple indexing
        uint4 t;
        t.x = f2tf32(v.x); t.y = f2tf32(v.y);
        t.z = f2tf32(v.z); t.w = f2tf32(v.w);
        ((uint4*)g_Wr)[i] = t;
    }

    // ---- dtype detect: 64 int64 words ----
    if (tid == 0) bad = 0;
    if (tid < NEXP) hist[tid] = 0;
    __syncthreads();
    if (tid < 64) {
        long long v = sel64[tid];
        if (v < 0 || v >= NEXP) atomicOr(&bad, 1);
    }
    __syncthreads();
    const int is64 = bad ? 0 : 1;

    // ---- load my 32 contiguous sel values into regs ----
    int v[32];
    if (is64) {
        const longlong2* p = (const longlong2*)sel64 + tid * 16;
#pragma unroll
        for (int i = 0; i < 16; i++) {
            longlong2 q = p[i];
            v[2 * i]     = (int)q.x;
            v[2 * i + 1] = (int)q.y;
        }
    } else {
        const int4* p = (const int4*)sel64 + tid * 8;
#pragma unroll
        for (int i = 0; i < 8; i++) {
            int4 q = p[i];
            v[4 * i] = q.x; v[4 * i + 1] = q.y;
            v[4 * i + 2] = q.z; v[4 * i + 3] = q.w;
        }
    }

    // ---- full histogram (smem atomics) + my-expert count ----
    int myc = 0;
#pragma unroll
    for (int i = 0; i < 32; i++) {
        atomicAdd(&hist[v[i]], 1);
        myc += (v[i] == e);
    }
    __syncthreads();

    // ---- padded scan over 64 experts ----
    if (tid < NEXP) {
        int pd = (hist[tid] + NODES_PER_CHUNK - 1) & ~(NODES_PER_CHUNK - 1);
        pads[tid] = pd;
        sc[tid] = pd;
    }
    __syncthreads();
#pragma unroll
    for (int d = 1; d < NEXP; d <<= 1) {
        int t = 0;
        if (tid < NEXP && tid >= d) t = sc[tid - d];
        __syncthreads();
        if (tid < NEXP) sc[tid] += t;
        __syncthreads();
    }
    const int offs_e = sc[e] - pads[e];
    const int cnt_e  = hist[e];
    const int pad_e  = pads[e];
    const int total  = sc[NEXP - 1];

    // ---- scan of per-thread match counts (256) ----
    tc[tid] = myc;
    __syncthreads();
#pragma unroll
    for (int d = 1; d < 256; d <<= 1) {
        int t = 0;
        if (tid >= d) t = tc[tid - d];
        __syncthreads();
        tc[tid] += t;
        __syncthreads();
    }
    int w = offs_e + tc[tid] - myc;

    // ---- compact my expert's nodes (global node order preserved) ----
#pragma unroll
    for (int i = 0; i < 32; i++)
        if (v[i] == e) g_sorted[w++] = tid * 32 + i;

    // ---- pads ----
    for (int i = cnt_e + tid; i < pad_e; i += 256)
        g_sorted[offs_e + i] = -1;

    // ---- chunk map: my chunks; CTA 0 fills the tail ----
    for (int c = offs_e / NODES_PER_CHUNK + tid;
         c < (offs_e + pad_e) / NODES_PER_CHUNK; c += 256)
        g_chunk_expert[c] = e;
    if (e == 0)
        for (int c = total / NODES_PER_CHUNK + tid; c < MAX_CHK; c += 256)
            g_chunk_expert[c] = -1;
}

// ---------------------------------------------------------------------------
// K_gemm: grouped GEMM (R9-proven, 23.2us), tf32 mma.sync + ldmatrix +
// 3-stage cp.async, pre-rounded W, single __syncthreads per k-tile.
// ---------------------------------------------------------------------------
extern __shared__ char smem[];

__global__ __launch_bounds__(256, 2)
void grouped_gemm_kernel(const float* __restrict__ x,
                         float* __restrict__ out) {
    const int e = g_chunk_expert[blockIdx.x];
    if (e < 0) return;

    int* snode = (int*)(smem + SMEM_NODE);
    const int tid  = threadIdx.x;
    const int lane = tid & 31;
    const int warp = tid >> 5;
    const int warp_m = (warp & 3) * 32;
    const int warp_n = (warp >> 2) * 64;

    if (tid < NODES_PER_CHUNK)
        snode[tid] = g_sorted[blockIdx.x * NODES_PER_CHUNK + tid];
    __syncthreads();

    const uint32_t sbase = smem_u32(smem);

    const float* xa[4];
    const float* wa[4];
    uint32_t da[4], db[4];
    int      asz[4];
    const float* Wre = g_Wr + (size_t)e * CH * CH;
#pragma unroll
    for (int i = 0; i < 4; i++) {
        int id  = tid + i * 256;
        int row = id >> 3;
        int cq  = id & 7;
        int node = snode[row >> 3];
        asz[i] = (node >= 0) ? 16 : 0;
        if (node < 0) node = 0;
        xa[i] = x + ((size_t)(row & 7) * N_NODES + node) * CH + cq * 4;
        wa[i] = Wre + (size_t)row * CH + cq * 4;
        da[i] = sbase + (uint32_t)row * ROW_BYTES + cq * 16;
        db[i] = sbase + (uint32_t)(128 * ROW_BYTES) + (uint32_t)row * ROW_BYTES + cq * 16;
    }

    uint32_t a_addr[2], b_addr[4];
    {
        int arow  = warp_m + (lane & 15);
        int abyte = (lane >> 4) * 16;
#pragma unroll
        for (int mt = 0; mt < 2; mt++)
            a_addr[mt] = sbase + (uint32_t)(arow + mt * 16) * ROW_BYTES + abyte;

        int brow  = warp_n + ((lane >> 4) << 3) + (lane & 7);
        int bbyte = ((lane >> 3) & 1) * 16;
#pragma unroll
        for (int p = 0; p < 4; p++)
            b_addr[p] = sbase + (uint32_t)(128 * ROW_BYTES)
                      + (uint32_t)(brow + p * 16) * ROW_BYTES + bbyte;
    }

    float acc[2][8][4];
#pragma unroll
    for (int mt = 0; mt < 2; mt++)
#pragma unroll
        for (int nt = 0; nt < 8; nt++)
#pragma unroll
            for (int i = 0; i < 4; i++) acc[mt][nt][i] = 0.0f;

    // prologue: issue tiles 0 and 1
#pragma unroll
    for (int t = 0; t < 2; t++) {
        uint32_t so = t * STAGE;
        int go = t * KT;
#pragma unroll
        for (int i = 0; i < 4; i++) {
            cp16(da[i] + so, xa[i] + go, asz[i]);
            cp16(db[i] + so, wa[i] + go, 16);
        }
        cp_commit();
    }

#pragma unroll
    for (int k = 0; k < 4; k++) {
        if (k < 3) cp_wait<1>();
        else       cp_wait<0>();
        __syncthreads();

        if (k + 2 < 4) {
            uint32_t so = ((k + 2) % NSTAGES) * STAGE;
            int go = (k + 2) * KT;
#pragma unroll
            for (int i = 0; i < 4; i++) {
                cp16(da[i] + so, xa[i] + go, asz[i]);
                cp16(db[i] + so, wa[i] + go, 16);
            }
            cp_commit();
        }

        const uint32_t so = (k % NSTAGES) * STAGE;
#pragma unroll
        for (int ks = 0; ks < 4; ks++) {
            uint32_t a[2][4], b[4][4];
#pragma unroll
            for (int mt = 0; mt < 2; mt++)
                ldsm_x4(a[mt], a_addr[mt] + so + ks * 32);
#pragma unroll
            for (int p = 0; p < 4; p++)
                ldsm_x4(b[p], b_addr[p] + so + ks * 32);
#pragma unroll
            for (int mt = 0; mt < 2; mt++)
#pragma unroll
                for (int nt = 0; nt < 8; nt++)
                    mma_tf32(acc[mt][nt], a[mt], &b[nt >> 1][(nt & 1) * 2]);
        }
    }

    const int g = lane >> 2;
    const int c = lane & 3;
#pragma unroll
    for (int mt = 0; mt < 2; mt++) {
#pragma unroll
        for (int half = 0; half < 2; half++) {
            int r = warp_m + mt * 16 + g + half * 8;
            int node = snode[r >> 3];
            if (node < 0) continue;
            float* o = out + ((size_t)(r & 7) * N_NODES + node) * CH + warp_n;
#pragma unroll
            for (int nt = 0; nt < 8; nt++) {
                float2 v2 = make_float2(acc[mt][nt][half * 2],
                                        acc[mt][nt][half * 2 + 1]);
                *(float2*)(o + nt * 8 + c * 2) = v2;
            }
        }
    }
}

// ---------------------------------------------------------------------------
extern "C" void kernel_launch(void* const* d_in, const int* in_sizes, int n_in,
                              void* d_out, int out_size) {
    const float*     x   = (const float*)d_in[0];
    const long long* sel = (const long long*)d_in[1];
    const float*     W   = (const float*)d_in[2];
    float*           out = (float*)d_out;

    static bool attr_set = false;
    if (!attr_set) {
        cudaFuncSetAttribute(grouped_gemm_kernel,
                             cudaFuncAttributeMaxDynamicSharedMemorySize,
                             SMEM_TOTAL);
        attr_set = true;
    }

    prep_kernel<<<NEXP, 256>>>(W, sel);
    grouped_gemm_kernel<<<MAX_CHK, 256, SMEM_TOTAL>>>(x, out);
}